// round 6
// baseline (speedup 1.0000x reference)
#include <cuda_runtime.h>
#include <cstdint>
#include <math.h>

#define ALPHA 1000.0f
#define NB 8192
#define ND 784
#define NH 256
#define NE 32
#define NK 512

// scratch (allocation-free rule: __device__ globals)
__device__ float g_h [NB * NH];
__device__ float g_h2[NB * NH];

// ---------------------------------------------------------------------------
// tf32 helpers (baseline PTX, sm_80+)
// ---------------------------------------------------------------------------
__device__ __forceinline__ uint32_t tf32_round(float x) {
    uint32_t u;
    asm("cvt.rna.tf32.f32 %0, %1;" : "=r"(u) : "f"(x));
    return u;
}

__device__ __forceinline__ void mma_tf32(float* d, const uint32_t* a, const uint32_t* b) {
    asm volatile(
        "mma.sync.aligned.m16n8k8.row.col.f32.tf32.tf32.f32 "
        "{%0,%1,%2,%3}, {%4,%5,%6,%7}, {%8,%9}, {%0,%1,%2,%3};"
        : "+f"(d[0]), "+f"(d[1]), "+f"(d[2]), "+f"(d[3])
        : "r"(a[0]), "r"(a[1]), "r"(a[2]), "r"(a[3]), "r"(b[0]), "r"(b[1]));
}

// ---------------------------------------------------------------------------
// 3xTF32 tensor-core GEMM: C[M,N] = A[M,K] @ W[K,N] + bias (+ReLU).
// CTA tile 128x64, K chunks of 32. 128 threads = 4 warps (2M x 2N),
// warp tile 64x32 (4 x 4 m16n8 tiles). 48KB smem -> 4 CTAs/SM.
// Fragment-major hi/lo smem blocks; all LDS/STS conflict-free.
// Requires M % 128 == 0; N, K arbitrary (guarded).
// ---------------------------------------------------------------------------
#define SA_HI 0
#define SA_LO 16384
#define SB_HI 32768
#define SB_LO 40960
#define GEMM_SMEM 49152

template <bool RELU>
__global__ __launch_bounds__(128, 4) void mma_gemm(
    const float* __restrict__ A, const float* __restrict__ W,
    const float* __restrict__ bias, float* __restrict__ C,
    int M, int N, int K)
{
    extern __shared__ char smem[];
    char* sAhi = smem + SA_HI;
    char* sAlo = smem + SA_LO;
    char* sBhi = smem + SB_HI;
    char* sBlo = smem + SB_LO;

    const int tid  = threadIdx.x;
    const int wid  = tid >> 5;
    const int lane = tid & 31;
    const int wm   = wid & 1;         // 0..1 (M halves of 64)
    const int wn   = (wid >> 1) & 1;  // 0..1 (N halves of 32)
    const int g    = lane >> 2;       // fragment group id
    const int c    = lane & 3;        // thread-in-group

    const int m0 = blockIdx.y * 128;
    const int n0 = blockIdx.x * 64;

    float acc[4][4][4];
#pragma unroll
    for (int mt = 0; mt < 4; mt++)
#pragma unroll
        for (int nt = 0; nt < 4; nt++)
#pragma unroll
            for (int i = 0; i < 4; i++) acc[mt][nt][i] = 0.f;

    const int nch = (K + 31) / 32;
    for (int t = 0; t < nch; t++) {
        const int k0 = t * 32;

        // ---- stage A: 32 blocks (mt 0..7, ks 0..3) x 32 lanes, hi/lo ----
#pragma unroll
        for (int i = 0; i < 8; i++) {
            const int slot = tid + i * 128;       // 0..1023
            const int blk  = slot >> 5;
            const int ln   = slot & 31;
            const int mt   = blk >> 2;
            const int ks   = blk & 3;
            const int gg   = ln >> 2;
            const int cc   = ln & 3;
            const int row  = m0 + mt * 16 + gg;
            const int k    = k0 + ks * 8 + cc;
            float v0 = 0.f, v1 = 0.f, v2 = 0.f, v3 = 0.f;
            if (k < K) {
                v0 = A[(size_t)row * K + k];
                v1 = A[(size_t)(row + 8) * K + k];
            }
            if (k + 4 < K) {
                v2 = A[(size_t)row * K + k + 4];
                v3 = A[(size_t)(row + 8) * K + k + 4];
            }
            uint4 hi, lo;
            hi.x = tf32_round(v0); lo.x = tf32_round(v0 - __uint_as_float(hi.x));
            hi.y = tf32_round(v1); lo.y = tf32_round(v1 - __uint_as_float(hi.y));
            hi.z = tf32_round(v2); lo.z = tf32_round(v2 - __uint_as_float(hi.z));
            hi.w = tf32_round(v3); lo.w = tf32_round(v3 - __uint_as_float(hi.w));
            *(uint4*)(sAhi + slot * 16) = hi;
            *(uint4*)(sAlo + slot * 16) = lo;
        }

        // ---- stage B: 32 blocks (nt 0..7, ks 0..3) x 32 lanes, hi/lo ----
#pragma unroll
        for (int i = 0; i < 8; i++) {
            const int slot = tid + i * 128;       // 0..1023
            const int blk  = slot >> 5;
            const int ln   = slot & 31;
            const int nt   = blk >> 2;
            const int ks   = blk & 3;
            const int gg   = ln >> 2;
            const int cc   = ln & 3;
            const int n    = n0 + nt * 8 + gg;
            const int k    = k0 + ks * 8 + cc;
            float b0 = 0.f, b1 = 0.f;
            if (n < N) {
                if (k < K)     b0 = W[(size_t)k * N + n];
                if (k + 4 < K) b1 = W[(size_t)(k + 4) * N + n];
            }
            uint2 hi, lo;
            hi.x = tf32_round(b0); lo.x = tf32_round(b0 - __uint_as_float(hi.x));
            hi.y = tf32_round(b1); lo.y = tf32_round(b1 - __uint_as_float(hi.y));
            *(uint2*)(sBhi + slot * 8) = hi;
            *(uint2*)(sBlo + slot * 8) = lo;
        }
        __syncthreads();

        // ---- compute: 4 k-steps, 16 tiles, 3 mma each ----
#pragma unroll
        for (int ks = 0; ks < 4; ks++) {
            uint4 ah[4], al[4];
#pragma unroll
            for (int mt = 0; mt < 4; mt++) {
                const int blk = ((wm * 4 + mt) * 4 + ks) * 32 + lane;
                ah[mt] = *(const uint4*)(sAhi + blk * 16);
                al[mt] = *(const uint4*)(sAlo + blk * 16);
            }
            uint2 bh[4], bl[4];
#pragma unroll
            for (int nt = 0; nt < 4; nt++) {
                const int blk = ((wn * 4 + nt) * 4 + ks) * 32 + lane;
                bh[nt] = *(const uint2*)(sBhi + blk * 8);
                bl[nt] = *(const uint2*)(sBlo + blk * 8);
            }
#pragma unroll
            for (int mt = 0; mt < 4; mt++)
#pragma unroll
                for (int nt = 0; nt < 4; nt++) {
                    mma_tf32(acc[mt][nt], (const uint32_t*)&ah[mt], (const uint32_t*)&bh[nt]);
                    mma_tf32(acc[mt][nt], (const uint32_t*)&ah[mt], (const uint32_t*)&bl[nt]);
                    mma_tf32(acc[mt][nt], (const uint32_t*)&al[mt], (const uint32_t*)&bh[nt]);
                }
        }
        __syncthreads();
    }

    // ---- epilogue: bias + relu, direct float2 stores ----
#pragma unroll
    for (int nt = 0; nt < 4; nt++) {
        const int col = n0 + (wn * 4 + nt) * 8 + 2 * c;
        if (col < N) {
            const float bx = __ldg(&bias[col]);
            const float by = __ldg(&bias[col + 1]);
#pragma unroll
            for (int mt = 0; mt < 4; mt++) {
                const int row = m0 + (wm * 4 + mt) * 16 + g;
                float2 lo_v, hi_v;
                lo_v.x = acc[mt][nt][0] + bx;
                lo_v.y = acc[mt][nt][1] + by;
                hi_v.x = acc[mt][nt][2] + bx;
                hi_v.y = acc[mt][nt][3] + by;
                if (RELU) {
                    lo_v.x = fmaxf(lo_v.x, 0.f); lo_v.y = fmaxf(lo_v.y, 0.f);
                    hi_v.x = fmaxf(hi_v.x, 0.f); hi_v.y = fmaxf(hi_v.y, 0.f);
                }
                *(float2*)&C[(size_t)row * N + col]       = lo_v;
                *(float2*)&C[(size_t)(row + 8) * N + col] = hi_v;
            }
        }
    }
}

// ---------------------------------------------------------------------------
// Fused distances + stable softmin.
// ---------------------------------------------------------------------------
#define REPS_STRIDE 36
#define DIST_SMEM_FLOATS (NK * REPS_STRIDE + 16 * NE + 256 + 32)

__global__ __launch_bounds__(256) void dist_softmin_kernel(
    const float* __restrict__ emb, const float* __restrict__ reps,
    float* __restrict__ weighted, float* __restrict__ distances)
{
    extern __shared__ float s[];
    float* reps_s = s;
    float* emb_s  = s + NK * REPS_STRIDE;
    float* red    = emb_s + 16 * NE;
    float* rmin   = red + 256;
    float* rsum   = rmin + 16;

    const int tid  = threadIdx.x;
    const int brow = blockIdx.x * 16;

    const float4* repsg = (const float4*)reps;
    for (int idx = tid; idx < NK * NE / 4; idx += 256) {
        const int k  = idx >> 3;
        const int e4 = idx & 7;
        ((float4*)&reps_s[k * REPS_STRIDE])[e4] = repsg[idx];
    }
    const float4* embg = (const float4*)(emb + (size_t)brow * NE);
    for (int idx = tid; idx < 16 * NE / 4; idx += 256)
        ((float4*)emb_s)[idx] = embg[idx];
    __syncthreads();

    const int row  = tid >> 4;
    const int lane = tid & 15;

    float er[NE];
#pragma unroll
    for (int e = 0; e < NE; e++) er[e] = emb_s[row * NE + e];

    float pd[32];
    float pmin = 3.4e38f;
#pragma unroll
    for (int j = 0; j < 32; j++) {
        const int k = j * 16 + lane;
        const float4* rp = (const float4*)&reps_s[k * REPS_STRIDE];
        float acc = 0.f;
#pragma unroll
        for (int e4 = 0; e4 < 8; e4++) {
            float4 r4 = rp[e4];
            float d0 = er[e4 * 4 + 0] - r4.x;
            float d1 = er[e4 * 4 + 1] - r4.y;
            float d2 = er[e4 * 4 + 2] - r4.z;
            float d3 = er[e4 * 4 + 3] - r4.w;
            acc += d0 * d0; acc += d1 * d1; acc += d2 * d2; acc += d3 * d3;
        }
        pd[j] = acc;
        pmin = fminf(pmin, acc);
    }

    red[tid] = pmin;
    __syncthreads();
    if (lane == 0) {
        float m = red[row * 16];
#pragma unroll
        for (int t = 1; t < 16; t++) m = fminf(m, red[row * 16 + t]);
        rmin[row] = m;
    }
    __syncthreads();
    const float mv = rmin[row];

    float pe[32];
    float psum = 0.f;
#pragma unroll
    for (int j = 0; j < 32; j++) {
        pe[j] = expf(-ALPHA * (pd[j] - mv));
        psum += pe[j];
    }
    red[tid] = psum;
    __syncthreads();
    if (lane == 0) {
        float su = 0.f;
#pragma unroll
        for (int t = 0; t < 16; t++) su += red[row * 16 + t];
        rsum[row] = su;
    }
    __syncthreads();
    const float inv = 1.0f / rsum[row];

    const size_t base = (size_t)(brow + row) * NK;
#pragma unroll
    for (int j = 0; j < 32; j++) {
        const int k = j * 16 + lane;
        const float dv = pd[j];
        distances[base + k] = dv;
        weighted[base + k]  = dv * pe[j] * inv;
    }
}

// ---------------------------------------------------------------------------
extern "C" void kernel_launch(void* const* d_in, const int* in_sizes, int n_in,
                              void* d_out, int out_size)
{
    const float* x    = (const float*)d_in[0];
    const float* reps = (const float*)d_in[1];
    const float* W1   = (const float*)d_in[2];
    const float* b1   = (const float*)d_in[3];
    const float* W2   = (const float*)d_in[4];
    const float* b2   = (const float*)d_in[5];
    const float* W3   = (const float*)d_in[6];
    const float* b3   = (const float*)d_in[7];
    const float* W4   = (const float*)d_in[8];
    const float* b4   = (const float*)d_in[9];

    float* out       = (float*)d_out;
    float* weighted  = out;
    float* distances = out + (size_t)NB * NK;
    float* rec       = out + 2 * (size_t)NB * NK;
    float* emb       = out + 2 * (size_t)NB * NK + (size_t)NB * ND;

    float *hbuf, *h2buf;
    cudaGetSymbolAddress((void**)&hbuf,  g_h);
    cudaGetSymbolAddress((void**)&h2buf, g_h2);

    cudaFuncSetAttribute(mma_gemm<true>,
                         cudaFuncAttributeMaxDynamicSharedMemorySize, GEMM_SMEM);
    cudaFuncSetAttribute(mma_gemm<false>,
                         cudaFuncAttributeMaxDynamicSharedMemorySize, GEMM_SMEM);
    const int dist_smem = DIST_SMEM_FLOATS * (int)sizeof(float);
    cudaFuncSetAttribute(dist_softmin_kernel,
                         cudaFuncAttributeMaxDynamicSharedMemorySize, dist_smem);

    // h = relu(x @ W1 + b1)           [8192,784] @ [784,256]
    mma_gemm<true ><<<dim3(4, NB / 128), 128, GEMM_SMEM>>>(x, W1, b1, hbuf, NB, NH, ND);
    // emb = h @ W2 + b2               [8192,256] @ [256,32]
    mma_gemm<false><<<dim3(1, NB / 128), 128, GEMM_SMEM>>>(hbuf, W2, b2, emb, NB, NE, NH);
    // h2 = relu(emb @ W3 + b3)        [8192,32] @ [32,256]
    mma_gemm<true ><<<dim3(4, NB / 128), 128, GEMM_SMEM>>>(emb, W3, b3, h2buf, NB, NH, NE);
    // rec = h2 @ W4 + b4              [8192,256] @ [256,784]
    mma_gemm<false><<<dim3(13, NB / 128), 128, GEMM_SMEM>>>(h2buf, W4, b4, rec, NB, ND, NH);
    // distances + softmin
    dist_softmin_kernel<<<NB / 16, 256, dist_smem>>>(emb, reps, weighted, distances);
}

// round 7
// speedup vs baseline: 2.0048x; 2.0048x over previous
#include <cuda_runtime.h>
#include <cstdint>
#include <math.h>

#define ALPHA 1000.0f
#define NB 8192
#define ND 784
#define NH 256
#define NE 32
#define NK 512

// ---------------------------------------------------------------------------
// Fragment-major hi/lo scratch (allocation-free rule: __device__ globals).
// A-frag layout: [mblk][KB][32 lanes][4]  (128 floats / block)
// B-frag layout: [nblk][KB][32 lanes][2]  (64 floats / block)
// ---------------------------------------------------------------------------
__device__ float g_xhi [NB * ND], g_xlo [NB * ND];     // x    A-frags, KB=98
__device__ float g_hhi [NB * NH], g_hlo [NB * NH];     // h    A-frags, KB=32
__device__ float g_ehi [NB * NE], g_elo [NB * NE];     // emb  A-frags, KB=4
__device__ float g_h2hi[NB * NH], g_h2lo[NB * NH];     // h2   A-frags, KB=32
__device__ float g_w1hi[32 * 98 * 64],  g_w1lo[32 * 98 * 64];    // W1 B-frags (N=256)
__device__ float g_w2hi[16 * 32 * 64],  g_w2lo[16 * 32 * 64];    // W2 (NPAD=128)
__device__ float g_w3hi[32 * 4 * 64],   g_w3lo[32 * 4 * 64];     // W3 (N=256)
__device__ float g_w4hi[112 * 32 * 64], g_w4lo[112 * 32 * 64];   // W4 (NPAD=896)

// ---------------------------------------------------------------------------
// helpers (baseline PTX only)
// ---------------------------------------------------------------------------
__device__ __forceinline__ uint32_t tf32_round(float x) {
    uint32_t u;
    asm("cvt.rna.tf32.f32 %0, %1;" : "=r"(u) : "f"(x));
    return u;
}
__device__ __forceinline__ void mma_tf32(float* d, const uint32_t* a, const uint32_t* b) {
    asm volatile(
        "mma.sync.aligned.m16n8k8.row.col.f32.tf32.tf32.f32 "
        "{%0,%1,%2,%3}, {%4,%5,%6,%7}, {%8,%9}, {%0,%1,%2,%3};"
        : "+f"(d[0]), "+f"(d[1]), "+f"(d[2]), "+f"(d[3])
        : "r"(a[0]), "r"(a[1]), "r"(a[2]), "r"(a[3]), "r"(b[0]), "r"(b[1]));
}
__device__ __forceinline__ uint32_t smem_u32(const void* p) {
    uint32_t a;
    asm("{ .reg .u64 t; cvta.to.shared.u64 t, %1; cvt.u32.u64 %0, t; }" : "=r"(a) : "l"(p));
    return a;
}
__device__ __forceinline__ void cp16(uint32_t dst, const void* src) {
    asm volatile("cp.async.cg.shared.global [%0], [%1], 16;" :: "r"(dst), "l"(src));
}

// write one value into A-fragment hi/lo buffers (for the next GEMM)
__device__ __forceinline__ void write_frag(float v, int m, int k, int KB,
                                           float* ghi, float* glo) {
    uint32_t hi = tf32_round(v);
    uint32_t lo = tf32_round(v - __uint_as_float(hi));
    const int mblk = m >> 4, kblk = k >> 3;
    const int ln   = ((m & 7) << 2) | (k & 3);
    const int slot = ((m >> 3) & 1) | (((k >> 2) & 1) << 1);
    const size_t o = (((size_t)mblk * KB + kblk) * 32 + ln) * 4 + slot;
    ((uint32_t*)ghi)[o] = hi;
    ((uint32_t*)glo)[o] = lo;
}

// ---------------------------------------------------------------------------
// split_A: A[M,K] row-major -> hi/lo A-fragments. Tile 32m x 64k per block.
// ---------------------------------------------------------------------------
__global__ __launch_bounds__(256) void split_A_kernel(
    const float* __restrict__ A, float* __restrict__ hi, float* __restrict__ lo,
    int K, int KB)
{
    __shared__ float s[32][65];
    const int tid = threadIdx.x;
    const int k0 = blockIdx.x * 64;
    const int m0 = blockIdx.y * 32;
#pragma unroll
    for (int i = 0; i < 8; i++) {
        const int idx = tid + i * 256;
        const int r = idx >> 6, cc = idx & 63;
        const int k = k0 + cc;
        s[r][cc] = (k < K) ? A[(size_t)(m0 + r) * K + k] : 0.f;
    }
    __syncthreads();
    const int mblk0 = blockIdx.y * 2, kblk0 = blockIdx.x * 8;
#pragma unroll
    for (int i = 0; i < 2; i++) {
        const int slot = tid + i * 256;       // 0..511
        const int mb = slot >> 8, kb = (slot >> 5) & 7, ln = slot & 31;
        if (kblk0 + kb < KB) {
            const int gg = ln >> 2, cc = ln & 3;
            const int mr = mb * 16 + gg, kc = kb * 8 + cc;
            const float v0 = s[mr][kc],     v1 = s[mr + 8][kc];
            const float v2 = s[mr][kc + 4], v3 = s[mr + 8][kc + 4];
            uint4 h4, l4;
            h4.x = tf32_round(v0); l4.x = tf32_round(v0 - __uint_as_float(h4.x));
            h4.y = tf32_round(v1); l4.y = tf32_round(v1 - __uint_as_float(h4.y));
            h4.z = tf32_round(v2); l4.z = tf32_round(v2 - __uint_as_float(h4.z));
            h4.w = tf32_round(v3); l4.w = tf32_round(v3 - __uint_as_float(h4.w));
            const size_t o = (((size_t)(mblk0 + mb) * KB + kblk0 + kb) * 32 + ln) * 4;
            *(uint4*)&hi[o] = h4;
            *(uint4*)&lo[o] = l4;
        }
    }
}

// ---------------------------------------------------------------------------
// split_B: W[K,N] row-major -> hi/lo B-fragments (zero-padded to NPAD).
// Tile 64k x 32n per block. grid = (NPAD/32, ceil(K/64)).
// ---------------------------------------------------------------------------
__global__ __launch_bounds__(256) void split_B_kernel(
    const float* __restrict__ W, float* __restrict__ hi, float* __restrict__ lo,
    int K, int N, int KB)
{
    __shared__ float s[64][33];
    const int tid = threadIdx.x;
    const int n0 = blockIdx.x * 32;
    const int k0 = blockIdx.y * 64;
#pragma unroll
    for (int i = 0; i < 8; i++) {
        const int idx = tid + i * 256;
        const int r = idx >> 5, cc = idx & 31;
        const int k = k0 + r, n = n0 + cc;
        s[r][cc] = (k < K && n < N) ? W[(size_t)k * N + n] : 0.f;
    }
    __syncthreads();
    const int nblk0 = blockIdx.x * 4, kblk0 = blockIdx.y * 8;
#pragma unroll
    for (int i = 0; i < 4; i++) {
        const int slot = tid + i * 256;       // 0..1023
        const int nb = slot >> 8, kb = (slot >> 5) & 7, ln = slot & 31;
        if (kblk0 + kb < KB) {
            const int gg = ln >> 2, cc = ln & 3;
            const float b0 = s[kb * 8 + cc][nb * 8 + gg];
            const float b1 = s[kb * 8 + cc + 4][nb * 8 + gg];
            uint2 h2, l2;
            h2.x = tf32_round(b0); l2.x = tf32_round(b0 - __uint_as_float(h2.x));
            h2.y = tf32_round(b1); l2.y = tf32_round(b1 - __uint_as_float(h2.y));
            const size_t o = (((size_t)(nblk0 + nb) * KB + kblk0 + kb) * 32 + ln) * 2;
            *(uint2*)&hi[o] = h2;
            *(uint2*)&lo[o] = l2;
        }
    }
}

// ---------------------------------------------------------------------------
// 3xTF32 GEMM on pre-split fragments, cp.async double-buffered.
// CTA 128x128, 256 threads = 8 warps (2M x 4N), warp tile 64x32, K-chunk 16.
// smem: 2 x (Ahi 8K | Alo 8K | Bhi 8K | Blo 8K) = 64 KB.
// OUTMODE: 0 = normal C, 1 = A-frags of next gemm, 2 = both.
// ---------------------------------------------------------------------------
#define GEMM_SMEM 65536

template <bool RELU, int OUTMODE>
__global__ __launch_bounds__(256, 2) void mma_gemm(
    const float* __restrict__ Ahi, const float* __restrict__ Alo,
    const float* __restrict__ Bhi, const float* __restrict__ Blo,
    const float* __restrict__ bias,
    float* __restrict__ Cn, float* __restrict__ Chi, float* __restrict__ Clo,
    int N, int KB, int KBOUT)
{
    extern __shared__ char smem[];
    const uint32_t sb32 = smem_u32(smem);
    const int tid = threadIdx.x, wid = tid >> 5, lane = tid & 31;
    const int wm = wid & 1, wn = wid >> 1;
    const int g = lane >> 2, c = lane & 3;
    const int m0 = blockIdx.y * 128, n0 = blockIdx.x * 128;
    const int mblk0 = blockIdx.y * 8, nblk0 = blockIdx.x * 16;

    float acc[4][4][4];
#pragma unroll
    for (int mt = 0; mt < 4; mt++)
#pragma unroll
        for (int nt = 0; nt < 4; nt++)
#pragma unroll
            for (int i = 0; i < 4; i++) acc[mt][nt][i] = 0.f;

    const int nch = KB >> 1;

    auto issue = [&](int t) {
        const uint32_t s = sb32 + (t & 1) * 32768;
        const int kb0 = t * 2;
#pragma unroll
        for (int i = 0; i < 2; i++) {
            const int idx = tid + i * 256;    // 0..511
            {   // A: per mblk 2 kblks = 1KB contiguous
                const int mb = idx >> 6, off = idx & 63;
                const size_t go = ((size_t)(mblk0 + mb) * KB + kb0) * 128 + off * 4;
                cp16(s + idx * 16,        Ahi + go);
                cp16(s + 8192 + idx * 16, Alo + go);
            }
            {   // B: per nblk 2 kblks = 512B contiguous
                const int nb = idx >> 5, off = idx & 31;
                const size_t go = ((size_t)(nblk0 + nb) * KB + kb0) * 64 + off * 4;
                cp16(s + 16384 + idx * 16, Bhi + go);
                cp16(s + 24576 + idx * 16, Blo + go);
            }
        }
    };

    issue(0);
    asm volatile("cp.async.commit_group;");

    for (int t = 0; t < nch; t++) {
        if (t + 1 < nch) {
            issue(t + 1);
            asm volatile("cp.async.commit_group;");
            asm volatile("cp.async.wait_group 1;");
        } else {
            asm volatile("cp.async.wait_group 0;");
        }
        __syncthreads();

        const char* s = smem + (t & 1) * 32768;
#pragma unroll
        for (int ks = 0; ks < 2; ks++) {
            uint4 ah[4], al[4];
#pragma unroll
            for (int mt = 0; mt < 4; mt++) {
                const int off = (((wm * 4 + mt) * 2 + ks) * 32 + lane) * 16;
                ah[mt] = *(const uint4*)(s + off);
                al[mt] = *(const uint4*)(s + 8192 + off);
            }
            uint2 bh[4], bl[4];
#pragma unroll
            for (int nt = 0; nt < 4; nt++) {
                const int off = (((wn * 4 + nt) * 2 + ks) * 32 + lane) * 8;
                bh[nt] = *(const uint2*)(s + 16384 + off);
                bl[nt] = *(const uint2*)(s + 24576 + off);
            }
#pragma unroll
            for (int mt = 0; mt < 4; mt++)
#pragma unroll
                for (int nt = 0; nt < 4; nt++) {
                    mma_tf32(acc[mt][nt], (const uint32_t*)&ah[mt], (const uint32_t*)&bh[nt]);
                    mma_tf32(acc[mt][nt], (const uint32_t*)&ah[mt], (const uint32_t*)&bl[nt]);
                    mma_tf32(acc[mt][nt], (const uint32_t*)&al[mt], (const uint32_t*)&bh[nt]);
                }
        }
        __syncthreads();
    }

    // ---- epilogue ----
#pragma unroll
    for (int nt = 0; nt < 4; nt++) {
        const int col = n0 + (wn * 4 + nt) * 8 + 2 * c;
        if (col < N) {
            const float bx = __ldg(&bias[col]);
            const float by = __ldg(&bias[col + 1]);
#pragma unroll
            for (int mt = 0; mt < 4; mt++) {
                const int row = m0 + (wm * 4 + mt) * 16 + g;
                float v00 = acc[mt][nt][0] + bx;
                float v01 = acc[mt][nt][1] + by;
                float v10 = acc[mt][nt][2] + bx;
                float v11 = acc[mt][nt][3] + by;
                if (RELU) {
                    v00 = fmaxf(v00, 0.f); v01 = fmaxf(v01, 0.f);
                    v10 = fmaxf(v10, 0.f); v11 = fmaxf(v11, 0.f);
                }
                if (OUTMODE == 0 || OUTMODE == 2) {
                    *(float2*)&Cn[(size_t)row * N + col]       = make_float2(v00, v01);
                    *(float2*)&Cn[(size_t)(row + 8) * N + col] = make_float2(v10, v11);
                }
                if (OUTMODE == 1 || OUTMODE == 2) {
                    write_frag(v00, row,     col,     KBOUT, Chi, Clo);
                    write_frag(v01, row,     col + 1, KBOUT, Chi, Clo);
                    write_frag(v10, row + 8, col,     KBOUT, Chi, Clo);
                    write_frag(v11, row + 8, col + 1, KBOUT, Chi, Clo);
                }
            }
        }
    }
}

// ---------------------------------------------------------------------------
// Fused distances + stable softmin (unchanged).
// ---------------------------------------------------------------------------
#define REPS_STRIDE 36
#define DIST_SMEM_FLOATS (NK * REPS_STRIDE + 16 * NE + 256 + 32)

__global__ __launch_bounds__(256) void dist_softmin_kernel(
    const float* __restrict__ emb, const float* __restrict__ reps,
    float* __restrict__ weighted, float* __restrict__ distances)
{
    extern __shared__ float s[];
    float* reps_s = s;
    float* emb_s  = s + NK * REPS_STRIDE;
    float* red    = emb_s + 16 * NE;
    float* rmin   = red + 256;
    float* rsum   = rmin + 16;

    const int tid  = threadIdx.x;
    const int brow = blockIdx.x * 16;

    const float4* repsg = (const float4*)reps;
    for (int idx = tid; idx < NK * NE / 4; idx += 256) {
        const int k  = idx >> 3;
        const int e4 = idx & 7;
        ((float4*)&reps_s[k * REPS_STRIDE])[e4] = repsg[idx];
    }
    const float4* embg = (const float4*)(emb + (size_t)brow * NE);
    for (int idx = tid; idx < 16 * NE / 4; idx += 256)
        ((float4*)emb_s)[idx] = embg[idx];
    __syncthreads();

    const int row  = tid >> 4;
    const int lane = tid & 15;

    float er[NE];
#pragma unroll
    for (int e = 0; e < NE; e++) er[e] = emb_s[row * NE + e];

    float pd[32];
    float pmin = 3.4e38f;
#pragma unroll
    for (int j = 0; j < 32; j++) {
        const int k = j * 16 + lane;
        const float4* rp = (const float4*)&reps_s[k * REPS_STRIDE];
        float acc = 0.f;
#pragma unroll
        for (int e4 = 0; e4 < 8; e4++) {
            float4 r4 = rp[e4];
            float d0 = er[e4 * 4 + 0] - r4.x;
            float d1 = er[e4 * 4 + 1] - r4.y;
            float d2 = er[e4 * 4 + 2] - r4.z;
            float d3 = er[e4 * 4 + 3] - r4.w;
            acc += d0 * d0; acc += d1 * d1; acc += d2 * d2; acc += d3 * d3;
        }
        pd[j] = acc;
        pmin = fminf(pmin, acc);
    }

    red[tid] = pmin;
    __syncthreads();
    if (lane == 0) {
        float m = red[row * 16];
#pragma unroll
        for (int t = 1; t < 16; t++) m = fminf(m, red[row * 16 + t]);
        rmin[row] = m;
    }
    __syncthreads();
    const float mv = rmin[row];

    float pe[32];
    float psum = 0.f;
#pragma unroll
    for (int j = 0; j < 32; j++) {
        pe[j] = expf(-ALPHA * (pd[j] - mv));
        psum += pe[j];
    }
    red[tid] = psum;
    __syncthreads();
    if (lane == 0) {
        float su = 0.f;
#pragma unroll
        for (int t = 0; t < 16; t++) su += red[row * 16 + t];
        rsum[row] = su;
    }
    __syncthreads();
    const float inv = 1.0f / rsum[row];

    const size_t base = (size_t)(brow + row) * NK;
#pragma unroll
    for (int j = 0; j < 32; j++) {
        const int k = j * 16 + lane;
        const float dv = pd[j];
        distances[base + k] = dv;
        weighted[base + k]  = dv * pe[j] * inv;
    }
}

// ---------------------------------------------------------------------------
extern "C" void kernel_launch(void* const* d_in, const int* in_sizes, int n_in,
                              void* d_out, int out_size)
{
    const float* x    = (const float*)d_in[0];
    const float* reps = (const float*)d_in[1];
    const float* W1   = (const float*)d_in[2];
    const float* b1   = (const float*)d_in[3];
    const float* W2   = (const float*)d_in[4];
    const float* b2   = (const float*)d_in[5];
    const float* W3   = (const float*)d_in[6];
    const float* b3   = (const float*)d_in[7];
    const float* W4   = (const float*)d_in[8];
    const float* b4   = (const float*)d_in[9];

    float* out       = (float*)d_out;
    float* weighted  = out;
    float* distances = out + (size_t)NB * NK;
    float* rec       = out + 2 * (size_t)NB * NK;
    float* emb       = out + 2 * (size_t)NB * NK + (size_t)NB * ND;

    float *xhi, *xlo, *hhi, *hlo, *ehi, *elo, *h2hi, *h2lo;
    float *w1hi, *w1lo, *w2hi, *w2lo, *w3hi, *w3lo, *w4hi, *w4lo;
    cudaGetSymbolAddress((void**)&xhi,  g_xhi);  cudaGetSymbolAddress((void**)&xlo,  g_xlo);
    cudaGetSymbolAddress((void**)&hhi,  g_hhi);  cudaGetSymbolAddress((void**)&hlo,  g_hlo);
    cudaGetSymbolAddress((void**)&ehi,  g_ehi);  cudaGetSymbolAddress((void**)&elo,  g_elo);
    cudaGetSymbolAddress((void**)&h2hi, g_h2hi); cudaGetSymbolAddress((void**)&h2lo, g_h2lo);
    cudaGetSymbolAddress((void**)&w1hi, g_w1hi); cudaGetSymbolAddress((void**)&w1lo, g_w1lo);
    cudaGetSymbolAddress((void**)&w2hi, g_w2hi); cudaGetSymbolAddress((void**)&w2lo, g_w2lo);
    cudaGetSymbolAddress((void**)&w3hi, g_w3hi); cudaGetSymbolAddress((void**)&w3lo, g_w3lo);
    cudaGetSymbolAddress((void**)&w4hi, g_w4hi); cudaGetSymbolAddress((void**)&w4lo, g_w4lo);

    cudaFuncSetAttribute(mma_gemm<true, 1>,
                         cudaFuncAttributeMaxDynamicSharedMemorySize, GEMM_SMEM);
    cudaFuncSetAttribute(mma_gemm<false, 2>,
                         cudaFuncAttributeMaxDynamicSharedMemorySize, GEMM_SMEM);
    cudaFuncSetAttribute(mma_gemm<false, 0>,
                         cudaFuncAttributeMaxDynamicSharedMemorySize, GEMM_SMEM);
    const int dist_smem = DIST_SMEM_FLOATS * (int)sizeof(float);
    cudaFuncSetAttribute(dist_softmin_kernel,
                         cudaFuncAttributeMaxDynamicSharedMemorySize, dist_smem);

    // ---- operand pre-splits ----
    split_A_kernel<<<dim3(13, NB / 32), 256>>>(x, xhi, xlo, ND, 98);
    split_B_kernel<<<dim3(8, 13), 256>>>(W1, w1hi, w1lo, ND, NH, 98);   // NPAD 256
    split_B_kernel<<<dim3(4, 4),  256>>>(W2, w2hi, w2lo, NH, NE, 32);   // NPAD 128
    split_B_kernel<<<dim3(8, 1),  256>>>(W3, w3hi, w3lo, NE, NH, 4);    // NPAD 256
    split_B_kernel<<<dim3(28, 4), 256>>>(W4, w4hi, w4lo, NH, ND, 32);   // NPAD 896

    // ---- GEMM chain ----
    // h = relu(x @ W1 + b1)  -> h fragments
    mma_gemm<true, 1><<<dim3(2, NB / 128), 256, GEMM_SMEM>>>(
        xhi, xlo, w1hi, w1lo, b1, nullptr, hhi, hlo, NH, 98, 32);
    // emb = h @ W2 + b2      -> normal emb + emb fragments
    mma_gemm<false, 2><<<dim3(1, NB / 128), 256, GEMM_SMEM>>>(
        hhi, hlo, w2hi, w2lo, b2, emb, ehi, elo, NE, 32, 4);
    // h2 = relu(emb @ W3 + b3) -> h2 fragments
    mma_gemm<true, 1><<<dim3(2, NB / 128), 256, GEMM_SMEM>>>(
        ehi, elo, w3hi, w3lo, b3, nullptr, h2hi, h2lo, NH, 4, 32);
    // rec = h2 @ W4 + b4     -> normal output
    mma_gemm<false, 0><<<dim3(7, NB / 128), 256, GEMM_SMEM>>>(
        h2hi, h2lo, w4hi, w4lo, b4, rec, nullptr, nullptr, ND, 32, 0);

    // ---- distances + softmin ----
    dist_softmin_kernel<<<NB / 16, 256, dist_smem>>>(emb, reps, weighted, distances);
}

// round 8
// speedup vs baseline: 2.2063x; 1.1005x over previous
#include <cuda_runtime.h>
#include <cstdint>
#include <math.h>

#define ALPHA 1000.0f
#define NB 8192
#define ND 784
#define NH 256
#define NE 32
#define NK 512

// ---------------------------------------------------------------------------
// Fragment-major hi/lo scratch (allocation-free rule: __device__ globals).
// A-frag layout: [mblk][KB][32 lanes][4]  (128 floats / block)
// B-frag layout: [nblk][KB][32 lanes][2]  (64 floats / block)
// ---------------------------------------------------------------------------
__device__ float g_xhi [NB * ND], g_xlo [NB * ND];     // x    A-frags, KB=98
__device__ float g_hhi [NB * NH], g_hlo [NB * NH];     // h    A-frags, KB=32
__device__ float g_ehi [NB * NE], g_elo [NB * NE];     // emb  A-frags, KB=4
__device__ float g_h2hi[NB * NH], g_h2lo[NB * NH];     // h2   A-frags, KB=32
__device__ float g_w1hi[32 * 98 * 64],  g_w1lo[32 * 98 * 64];    // W1 (N=256)
__device__ float g_w2hi[4 * 32 * 64],   g_w2lo[4 * 32 * 64];     // W2 (NPAD=32)
__device__ float g_w3hi[32 * 4 * 64],   g_w3lo[32 * 4 * 64];     // W3 (N=256)
__device__ float g_w4hi[112 * 32 * 64], g_w4lo[112 * 32 * 64];   // W4 (NPAD=896)

// ---------------------------------------------------------------------------
// helpers (baseline PTX only)
// ---------------------------------------------------------------------------
__device__ __forceinline__ uint32_t tf32_round(float x) {
    uint32_t u;
    asm("cvt.rna.tf32.f32 %0, %1;" : "=r"(u) : "f"(x));
    return u;
}
__device__ __forceinline__ void mma_tf32(float* d, const uint32_t* a, const uint32_t* b) {
    asm volatile(
        "mma.sync.aligned.m16n8k8.row.col.f32.tf32.tf32.f32 "
        "{%0,%1,%2,%3}, {%4,%5,%6,%7}, {%8,%9}, {%0,%1,%2,%3};"
        : "+f"(d[0]), "+f"(d[1]), "+f"(d[2]), "+f"(d[3])
        : "r"(a[0]), "r"(a[1]), "r"(a[2]), "r"(a[3]), "r"(b[0]), "r"(b[1]));
}
__device__ __forceinline__ uint32_t smem_u32(const void* p) {
    uint32_t a;
    asm("{ .reg .u64 t; cvta.to.shared.u64 t, %1; cvt.u32.u64 %0, t; }" : "=r"(a) : "l"(p));
    return a;
}
__device__ __forceinline__ void cp16(uint32_t dst, const void* src) {
    asm volatile("cp.async.cg.shared.global [%0], [%1], 16;" :: "r"(dst), "l"(src));
}

// write one value into A-fragment hi/lo buffers (for the next GEMM)
__device__ __forceinline__ void write_frag(float v, int m, int k, int KB,
                                           float* ghi, float* glo) {
    uint32_t hi = tf32_round(v);
    uint32_t lo = tf32_round(v - __uint_as_float(hi));
    const int mblk = m >> 4, kblk = k >> 3;
    const int ln   = ((m & 7) << 2) | (k & 3);
    const int slot = ((m >> 3) & 1) | (((k >> 2) & 1) << 1);
    const size_t o = (((size_t)mblk * KB + kblk) * 32 + ln) * 4 + slot;
    ((uint32_t*)ghi)[o] = hi;
    ((uint32_t*)glo)[o] = lo;
}

// ---------------------------------------------------------------------------
// split_A: A[M,K] row-major -> hi/lo A-fragments. Tile 32m x 64k per block.
// ---------------------------------------------------------------------------
__global__ __launch_bounds__(256) void split_A_kernel(
    const float* __restrict__ A, float* __restrict__ hi, float* __restrict__ lo,
    int K, int KB)
{
    __shared__ float s[32][65];
    const int tid = threadIdx.x;
    const int k0 = blockIdx.x * 64;
    const int m0 = blockIdx.y * 32;
#pragma unroll
    for (int i = 0; i < 8; i++) {
        const int idx = tid + i * 256;
        const int r = idx >> 6, cc = idx & 63;
        const int k = k0 + cc;
        s[r][cc] = (k < K) ? A[(size_t)(m0 + r) * K + k] : 0.f;
    }
    __syncthreads();
    const int mblk0 = blockIdx.y * 2, kblk0 = blockIdx.x * 8;
#pragma unroll
    for (int i = 0; i < 2; i++) {
        const int slot = tid + i * 256;       // 0..511
        const int mb = slot >> 8, kb = (slot >> 5) & 7, ln = slot & 31;
        if (kblk0 + kb < KB) {
            const int gg = ln >> 2, cc = ln & 3;
            const int mr = mb * 16 + gg, kc = kb * 8 + cc;
            const float v0 = s[mr][kc],     v1 = s[mr + 8][kc];
            const float v2 = s[mr][kc + 4], v3 = s[mr + 8][kc + 4];
            uint4 h4, l4;
            h4.x = tf32_round(v0); l4.x = tf32_round(v0 - __uint_as_float(h4.x));
            h4.y = tf32_round(v1); l4.y = tf32_round(v1 - __uint_as_float(h4.y));
            h4.z = tf32_round(v2); l4.z = tf32_round(v2 - __uint_as_float(h4.z));
            h4.w = tf32_round(v3); l4.w = tf32_round(v3 - __uint_as_float(h4.w));
            const size_t o = (((size_t)(mblk0 + mb) * KB + kblk0 + kb) * 32 + ln) * 4;
            *(uint4*)&hi[o] = h4;
            *(uint4*)&lo[o] = l4;
        }
    }
}

// ---------------------------------------------------------------------------
// merged split_B for all 4 weights: W[K,N] -> hi/lo B-fragments (pad to NPAD).
// blockIdx.z selects the weight; oversized blocks exit early.
// Tile 64k x 32n per block.
// ---------------------------------------------------------------------------
struct SplitBArgs {
    const float* W[4];
    float* hi[4];
    float* lo[4];
    int K[4], N[4], KB[4], gx[4], gy[4];
};

__global__ __launch_bounds__(256) void split_B4_kernel(SplitBArgs a)
{
    const int z = blockIdx.z;
    if ((int)blockIdx.x >= a.gx[z] || (int)blockIdx.y >= a.gy[z]) return;
    const float* __restrict__ W = a.W[z];
    float* __restrict__ hi = a.hi[z];
    float* __restrict__ lo = a.lo[z];
    const int K = a.K[z], N = a.N[z], KB = a.KB[z];

    __shared__ float s[64][33];
    const int tid = threadIdx.x;
    const int n0 = blockIdx.x * 32;
    const int k0 = blockIdx.y * 64;
#pragma unroll
    for (int i = 0; i < 8; i++) {
        const int idx = tid + i * 256;
        const int r = idx >> 5, cc = idx & 31;
        const int k = k0 + r, n = n0 + cc;
        s[r][cc] = (k < K && n < N) ? W[(size_t)k * N + n] : 0.f;
    }
    __syncthreads();
    const int nblk0 = blockIdx.x * 4, kblk0 = blockIdx.y * 8;
#pragma unroll
    for (int i = 0; i < 4; i++) {
        const int slot = tid + i * 256;       // 0..1023
        const int nb = slot >> 8, kb = (slot >> 5) & 7, ln = slot & 31;
        if (kblk0 + kb < KB) {
            const int gg = ln >> 2, cc = ln & 3;
            const float b0 = s[kb * 8 + cc][nb * 8 + gg];
            const float b1 = s[kb * 8 + cc + 4][nb * 8 + gg];
            uint2 h2, l2;
            h2.x = tf32_round(b0); l2.x = tf32_round(b0 - __uint_as_float(h2.x));
            h2.y = tf32_round(b1); l2.y = tf32_round(b1 - __uint_as_float(h2.y));
            const size_t o = (((size_t)(nblk0 + nb) * KB + kblk0 + kb) * 32 + ln) * 2;
            *(uint2*)&hi[o] = h2;
            *(uint2*)&lo[o] = l2;
        }
    }
}

// ---------------------------------------------------------------------------
// 3xTF32 GEMM on pre-split fragments, cp.async double-buffered.
// CTA tile 128 x (NBLKS*8), 256 threads = 8 warps (2M x 4N),
// warp tile 64 x (NTW*8), K-chunk 16.
// smem: 2 stages x 32KB (Ahi 8K | Alo 8K | Bhi ≤8K | Blo ≤8K).
// OUTMODE: 0 = normal C, 1 = A-frags of next gemm, 2 = both.
// ---------------------------------------------------------------------------
#define GEMM_SMEM 65536

template <bool RELU, int OUTMODE, int NBLKS>
__global__ __launch_bounds__(256, 2) void mma_gemm(
    const float* __restrict__ Ahi, const float* __restrict__ Alo,
    const float* __restrict__ Bhi, const float* __restrict__ Blo,
    const float* __restrict__ bias,
    float* __restrict__ Cn, float* __restrict__ Chi, float* __restrict__ Clo,
    int N, int KB, int KBOUT)
{
    constexpr int NTW = NBLKS / 4;    // nblks per warp
    extern __shared__ char smem[];
    const uint32_t sb32 = smem_u32(smem);
    const int tid = threadIdx.x, wid = tid >> 5, lane = tid & 31;
    const int wm = wid & 1, wn = wid >> 1;
    const int g = lane >> 2, c = lane & 3;
    const int m0 = blockIdx.y * 128, n0 = blockIdx.x * NBLKS * 8;
    const int mblk0 = blockIdx.y * 8, nblk0 = blockIdx.x * NBLKS;

    float acc[4][NTW][4];
#pragma unroll
    for (int mt = 0; mt < 4; mt++)
#pragma unroll
        for (int nt = 0; nt < NTW; nt++)
#pragma unroll
            for (int i = 0; i < 4; i++) acc[mt][nt][i] = 0.f;

    const int nch = KB >> 1;

    auto issue = [&](int t) {
        const uint32_t s = sb32 + (t & 1) * 32768;
        const int kb0 = t * 2;
        // A: 512 cp16 (8 mblks x 2 kblks x 128 floats)
#pragma unroll
        for (int i = 0; i < 2; i++) {
            const int idx = tid + i * 256;    // 0..511
            const int mb = idx >> 6, off = idx & 63;
            const size_t go = ((size_t)(mblk0 + mb) * KB + kb0) * 128 + off * 4;
            cp16(s + idx * 16,        Ahi + go);
            cp16(s + 8192 + idx * 16, Alo + go);
        }
        // B: NBLKS*32 cp16 (NBLKS nblks x 2 kblks x 64 floats)
#pragma unroll
        for (int idx = tid; idx < NBLKS * 32; idx += 256) {
            const int nb = idx >> 5, off = idx & 31;
            const size_t go = ((size_t)(nblk0 + nb) * KB + kb0) * 64 + off * 4;
            cp16(s + 16384 + idx * 16, Bhi + go);
            cp16(s + 24576 + idx * 16, Blo + go);
        }
    };

    issue(0);
    asm volatile("cp.async.commit_group;");

    for (int t = 0; t < nch; t++) {
        if (t + 1 < nch) {
            issue(t + 1);
            asm volatile("cp.async.commit_group;");
            asm volatile("cp.async.wait_group 1;");
        } else {
            asm volatile("cp.async.wait_group 0;");
        }
        __syncthreads();

        const char* s = smem + (t & 1) * 32768;
#pragma unroll
        for (int ks = 0; ks < 2; ks++) {
            uint4 ah[4], al[4];
#pragma unroll
            for (int mt = 0; mt < 4; mt++) {
                const int off = (((wm * 4 + mt) * 2 + ks) * 32 + lane) * 16;
                ah[mt] = *(const uint4*)(s + off);
                al[mt] = *(const uint4*)(s + 8192 + off);
            }
            uint2 bh[NTW], bl[NTW];
#pragma unroll
            for (int nt = 0; nt < NTW; nt++) {
                const int off = (((wn * NTW + nt) * 2 + ks) * 32 + lane) * 8;
                bh[nt] = *(const uint2*)(s + 16384 + off);
                bl[nt] = *(const uint2*)(s + 24576 + off);
            }
#pragma unroll
            for (int mt = 0; mt < 4; mt++)
#pragma unroll
                for (int nt = 0; nt < NTW; nt++) {
                    mma_tf32(acc[mt][nt], (const uint32_t*)&ah[mt], (const uint32_t*)&bh[nt]);
                    mma_tf32(acc[mt][nt], (const uint32_t*)&ah[mt], (const uint32_t*)&bl[nt]);
                    mma_tf32(acc[mt][nt], (const uint32_t*)&al[mt], (const uint32_t*)&bh[nt]);
                }
        }
        __syncthreads();
    }

    // ---- epilogue ----
#pragma unroll
    for (int nt = 0; nt < NTW; nt++) {
        const int col = n0 + (wn * NTW + nt) * 8 + 2 * c;
        if (col < N) {
            const float bx = __ldg(&bias[col]);
            const float by = __ldg(&bias[col + 1]);
#pragma unroll
            for (int mt = 0; mt < 4; mt++) {
                const int row = m0 + (wm * 4 + mt) * 16 + g;
                float v00 = acc[mt][nt][0] + bx;
                float v01 = acc[mt][nt][1] + by;
                float v10 = acc[mt][nt][2] + bx;
                float v11 = acc[mt][nt][3] + by;
                if (RELU) {
                    v00 = fmaxf(v00, 0.f); v01 = fmaxf(v01, 0.f);
                    v10 = fmaxf(v10, 0.f); v11 = fmaxf(v11, 0.f);
                }
                if (OUTMODE == 0 || OUTMODE == 2) {
                    *(float2*)&Cn[(size_t)row * N + col]       = make_float2(v00, v01);
                    *(float2*)&Cn[(size_t)(row + 8) * N + col] = make_float2(v10, v11);
                }
                if (OUTMODE == 1 || OUTMODE == 2) {
                    write_frag(v00, row,     col,     KBOUT, Chi, Clo);
                    write_frag(v01, row,     col + 1, KBOUT, Chi, Clo);
                    write_frag(v10, row + 8, col,     KBOUT, Chi, Clo);
                    write_frag(v11, row + 8, col + 1, KBOUT, Chi, Clo);
                }
            }
        }
    }
}

// ---------------------------------------------------------------------------
// Fused distances + stable softmin. 64 rows/block in 4 groups of 16;
// cluster reps staged once per block.
// ---------------------------------------------------------------------------
#define REPS_STRIDE 36
#define DIST_SMEM_FLOATS (NK * REPS_STRIDE + 16 * NE + 256 + 32)

__global__ __launch_bounds__(256) void dist_softmin_kernel(
    const float* __restrict__ emb, const float* __restrict__ reps,
    float* __restrict__ weighted, float* __restrict__ distances)
{
    extern __shared__ float s[];
    float* reps_s = s;
    float* emb_s  = s + NK * REPS_STRIDE;
    float* red    = emb_s + 16 * NE;
    float* rmin   = red + 256;
    float* rsum   = rmin + 16;

    const int tid  = threadIdx.x;
    const int row  = tid >> 4;
    const int lane = tid & 15;

    // stage cluster reps once
    const float4* repsg = (const float4*)reps;
    for (int idx = tid; idx < NK * NE / 4; idx += 256) {
        const int k  = idx >> 3;
        const int e4 = idx & 7;
        ((float4*)&reps_s[k * REPS_STRIDE])[e4] = repsg[idx];
    }

    for (int grp = 0; grp < 4; grp++) {
        const int brow = blockIdx.x * 64 + grp * 16;
        __syncthreads();   // reps ready (grp 0) / previous group done with smem
        const float4* embg = (const float4*)(emb + (size_t)brow * NE);
        for (int idx = tid; idx < 16 * NE / 4; idx += 256)
            ((float4*)emb_s)[idx] = embg[idx];
        __syncthreads();

        float er[NE];
#pragma unroll
        for (int e = 0; e < NE; e++) er[e] = emb_s[row * NE + e];

        float pd[32];
        float pmin = 3.4e38f;
#pragma unroll
        for (int j = 0; j < 32; j++) {
            const int k = j * 16 + lane;
            const float4* rp = (const float4*)&reps_s[k * REPS_STRIDE];
            float acc = 0.f;
#pragma unroll
            for (int e4 = 0; e4 < 8; e4++) {
                float4 r4 = rp[e4];
                float d0 = er[e4 * 4 + 0] - r4.x;
                float d1 = er[e4 * 4 + 1] - r4.y;
                float d2 = er[e4 * 4 + 2] - r4.z;
                float d3 = er[e4 * 4 + 3] - r4.w;
                acc += d0 * d0; acc += d1 * d1; acc += d2 * d2; acc += d3 * d3;
            }
            pd[j] = acc;
            pmin = fminf(pmin, acc);
        }

        red[tid] = pmin;
        __syncthreads();
        if (lane == 0) {
            float m = red[row * 16];
#pragma unroll
            for (int t = 1; t < 16; t++) m = fminf(m, red[row * 16 + t]);
            rmin[row] = m;
        }
        __syncthreads();
        const float mv = rmin[row];

        float pe[32];
        float psum = 0.f;
#pragma unroll
        for (int j = 0; j < 32; j++) {
            pe[j] = expf(-ALPHA * (pd[j] - mv));
            psum += pe[j];
        }
        red[tid] = psum;
        __syncthreads();
        if (lane == 0) {
            float su = 0.f;
#pragma unroll
            for (int t = 0; t < 16; t++) su += red[row * 16 + t];
            rsum[row] = su;
        }
        __syncthreads();
        const float inv = 1.0f / rsum[row];

        const size_t base = (size_t)(brow + row) * NK;
#pragma unroll
        for (int j = 0; j < 32; j++) {
            const int k = j * 16 + lane;
            const float dv = pd[j];
            distances[base + k] = dv;
            weighted[base + k]  = dv * pe[j] * inv;
        }
    }
}

// ---------------------------------------------------------------------------
extern "C" void kernel_launch(void* const* d_in, const int* in_sizes, int n_in,
                              void* d_out, int out_size)
{
    const float* x    = (const float*)d_in[0];
    const float* reps = (const float*)d_in[1];
    const float* W1   = (const float*)d_in[2];
    const float* b1   = (const float*)d_in[3];
    const float* W2   = (const float*)d_in[4];
    const float* b2   = (const float*)d_in[5];
    const float* W3   = (const float*)d_in[6];
    const float* b3   = (const float*)d_in[7];
    const float* W4   = (const float*)d_in[8];
    const float* b4   = (const float*)d_in[9];

    float* out       = (float*)d_out;
    float* weighted  = out;
    float* distances = out + (size_t)NB * NK;
    float* rec       = out + 2 * (size_t)NB * NK;
    float* emb       = out + 2 * (size_t)NB * NK + (size_t)NB * ND;

    float *xhi, *xlo, *hhi, *hlo, *ehi, *elo, *h2hi, *h2lo;
    float *w1hi, *w1lo, *w2hi, *w2lo, *w3hi, *w3lo, *w4hi, *w4lo;
    cudaGetSymbolAddress((void**)&xhi,  g_xhi);  cudaGetSymbolAddress((void**)&xlo,  g_xlo);
    cudaGetSymbolAddress((void**)&hhi,  g_hhi);  cudaGetSymbolAddress((void**)&hlo,  g_hlo);
    cudaGetSymbolAddress((void**)&ehi,  g_ehi);  cudaGetSymbolAddress((void**)&elo,  g_elo);
    cudaGetSymbolAddress((void**)&h2hi, g_h2hi); cudaGetSymbolAddress((void**)&h2lo, g_h2lo);
    cudaGetSymbolAddress((void**)&w1hi, g_w1hi); cudaGetSymbolAddress((void**)&w1lo, g_w1lo);
    cudaGetSymbolAddress((void**)&w2hi, g_w2hi); cudaGetSymbolAddress((void**)&w2lo, g_w2lo);
    cudaGetSymbolAddress((void**)&w3hi, g_w3hi); cudaGetSymbolAddress((void**)&w3lo, g_w3lo);
    cudaGetSymbolAddress((void**)&w4hi, g_w4hi); cudaGetSymbolAddress((void**)&w4lo, g_w4lo);

    cudaFuncSetAttribute((const void*)mma_gemm<true, 1, 8>,
                         cudaFuncAttributeMaxDynamicSharedMemorySize, GEMM_SMEM);
    cudaFuncSetAttribute((const void*)mma_gemm<false, 2, 4>,
                         cudaFuncAttributeMaxDynamicSharedMemorySize, GEMM_SMEM);
    cudaFuncSetAttribute((const void*)mma_gemm<false, 0, 16>,
                         cudaFuncAttributeMaxDynamicSharedMemorySize, GEMM_SMEM);
    const int dist_smem = DIST_SMEM_FLOATS * (int)sizeof(float);
    cudaFuncSetAttribute(dist_softmin_kernel,
                         cudaFuncAttributeMaxDynamicSharedMemorySize, dist_smem);

    // ---- operand pre-splits ----
    split_A_kernel<<<dim3(13, NB / 32), 256>>>(x, xhi, xlo, ND, 98);
    {
        SplitBArgs a;
        a.W[0] = W1;   a.hi[0] = w1hi; a.lo[0] = w1lo;
        a.K[0] = ND;   a.N[0] = NH;    a.KB[0] = 98; a.gx[0] = 8;  a.gy[0] = 13;
        a.W[1] = W2;   a.hi[1] = w2hi; a.lo[1] = w2lo;
        a.K[1] = NH;   a.N[1] = NE;    a.KB[1] = 32; a.gx[1] = 1;  a.gy[1] = 4;
        a.W[2] = W3;   a.hi[2] = w3hi; a.lo[2] = w3lo;
        a.K[2] = NE;   a.N[2] = NH;    a.KB[2] = 4;  a.gx[2] = 8;  a.gy[2] = 1;
        a.W[3] = W4;   a.hi[3] = w4hi; a.lo[3] = w4lo;
        a.K[3] = NH;   a.N[3] = ND;    a.KB[3] = 32; a.gx[3] = 28; a.gy[3] = 4;
        split_B4_kernel<<<dim3(28, 13, 4), 256>>>(a);
    }

    // ---- GEMM chain ----
    // h = relu(x @ W1 + b1)  -> h fragments          (N-tile 64, 256 CTAs)
    mma_gemm<true, 1, 8><<<dim3(4, NB / 128), 256, GEMM_SMEM>>>(
        xhi, xlo, w1hi, w1lo, b1, nullptr, hhi, hlo, NH, 98, 32);
    // emb = h @ W2 + b2      -> normal emb + emb fragments (N-tile 32, no pad waste)
    mma_gemm<false, 2, 4><<<dim3(1, NB / 128), 256, GEMM_SMEM>>>(
        hhi, hlo, w2hi, w2lo, b2, emb, ehi, elo, NE, 32, 4);
    // h2 = relu(emb @ W3 + b3) -> h2 fragments       (N-tile 64, 256 CTAs)
    mma_gemm<true, 1, 8><<<dim3(4, NB / 128), 256, GEMM_SMEM>>>(
        ehi, elo, w3hi, w3lo, b3, nullptr, h2hi, h2lo, NH, 4, 32);
    // rec = h2 @ W4 + b4     -> normal output        (N-tile 128, 448 CTAs)
    mma_gemm<false, 0, 16><<<dim3(7, NB / 128), 256, GEMM_SMEM>>>(
        h2hi, h2lo, w4hi, w4lo, b4, rec, nullptr, nullptr, ND, 32, 0);

    // ---- distances + softmin ----
    dist_softmin_kernel<<<NB / 64, 256, dist_smem>>>(emb, reps, weighted, distances);
}